// round 1
// baseline (speedup 1.0000x reference)
#include <cuda_runtime.h>
#include <math.h>

#define BB 2
#define LL 2048
#define DM 512
#define DI 1024
#define DS 16
#define NTOK (BB*LL)   // 4096

// ---------------- scratch (static device arrays; no runtime allocation) ----
__device__ float g_xn[NTOK*DM];              // layernorm output       8 MB
__device__ float g_xz[2][NTOK*2*DI];         // in-proj out (xi|z)   128 MB
__device__ float g_xi[2][NTOK*DI];           // conv+silu out         32 MB
__device__ float g_xdbl[2][NTOK*64];         // x_proj out             2 MB
__device__ float g_dt[2][NTOK*DI];           // softplus(dt)          32 MB
__device__ float g_y[2][NTOK*DI];            // scan output           32 MB
__device__ float g_yc[NTOK*DM];              // combined y @ out_w     8 MB

// ---------------- layernorm ------------------------------------------------
__global__ void ln_kernel(const float* __restrict__ x,
                          const float* __restrict__ g,
                          const float* __restrict__ b) {
    int row = blockIdx.x;
    const float* xr = x + row*DM;
    int tid = threadIdx.x;
    float v0 = xr[tid], v1 = xr[tid+256];
    __shared__ float s1[256], s2[256];
    s1[tid] = v0+v1; s2[tid] = v0*v0+v1*v1;
    __syncthreads();
    for (int o=128;o>0;o>>=1){
        if (tid<o){ s1[tid]+=s1[tid+o]; s2[tid]+=s2[tid+o]; }
        __syncthreads();
    }
    float mu = s1[0]*(1.0f/DM);
    float var = s2[0]*(1.0f/DM) - mu*mu;
    float rs = rsqrtf(var + 1e-5f);
    g_xn[row*DM+tid]     = (v0-mu)*rs*g[tid]     + b[tid];
    g_xn[row*DM+tid+256] = (v1-mu)*rs*g[tid+256] + b[tid+256];
}

// ---------------- fp32 SGEMM 128x128x8, 256 threads, 8x8 per thread --------
// epi: 0 = C = A@B
//      1 = C += A@B
//      2 = C = softplus(A@B + bias)
//      3 = C = A@B + bias + res
__global__ __launch_bounds__(256) void sgemm(
    const float* __restrict__ A, int lda,
    const float* __restrict__ B, int ldb,
    float* __restrict__ C, int ldc,
    int N, int K,
    const float* __restrict__ bias,
    const float* __restrict__ res, int ldres, int epi)
{
    __shared__ float As[8][128];
    __shared__ float Bs[8][128];
    int tid = threadIdx.x;
    int bm = blockIdx.y*128, bn = blockIdx.x*128;
    int arow = tid >> 1;             // 0..127
    int acol = (tid & 1) * 4;        // 0 or 4
    int brow = tid >> 5;             // 0..7
    int bcol = (tid & 31) * 4;       // 0..124
    int ty = tid >> 4, tx = tid & 15;

    float acc[8][8];
    #pragma unroll
    for (int i=0;i<8;i++)
        #pragma unroll
        for (int j=0;j<8;j++) acc[i][j]=0.f;

    for (int k0=0; k0<K; k0+=8) {
        float4 a4 = *(const float4*)(A + (long)(bm+arow)*lda + k0 + acol);
        As[acol+0][arow]=a4.x; As[acol+1][arow]=a4.y;
        As[acol+2][arow]=a4.z; As[acol+3][arow]=a4.w;
        float4 b4 = make_float4(0.f,0.f,0.f,0.f);
        if (bn + bcol < N)
            b4 = *(const float4*)(B + (long)(k0+brow)*ldb + bn + bcol);
        *(float4*)&Bs[brow][bcol] = b4;
        __syncthreads();
        #pragma unroll
        for (int k=0;k<8;k++){
            float4 ra0 = *(float4*)&As[k][ty*8];
            float4 ra1 = *(float4*)&As[k][ty*8+4];
            float4 rb0 = *(float4*)&Bs[k][tx*8];
            float4 rb1 = *(float4*)&Bs[k][tx*8+4];
            float ra[8] = {ra0.x,ra0.y,ra0.z,ra0.w,ra1.x,ra1.y,ra1.z,ra1.w};
            float rb[8] = {rb0.x,rb0.y,rb0.z,rb0.w,rb1.x,rb1.y,rb1.z,rb1.w};
            #pragma unroll
            for (int i=0;i<8;i++)
                #pragma unroll
                for (int j=0;j<8;j++)
                    acc[i][j] = fmaf(ra[i], rb[j], acc[i][j]);
        }
        __syncthreads();
    }

    #pragma unroll
    for (int i=0;i<8;i++){
        long r = bm + ty*8 + i;
        #pragma unroll
        for (int j=0;j<8;j++){
            int c = bn + tx*8 + j;
            if (c >= N) continue;
            float v = acc[i][j];
            if (epi==1)      v += C[r*ldc+c];
            else if (epi==2){ v += bias[c]; v = (v>20.f)? v : log1pf(expf(v)); }
            else if (epi==3)  v += bias[c] + res[r*ldres+c];
            C[r*ldc+c]=v;
        }
    }
}

// ---------------- depthwise conv (causal fwd / anti-causal bwd) + SiLU -----
__global__ void conv_kernel(const float* __restrict__ w,
                            const float* __restrict__ bias, int dir){
    int idx = blockIdx.x*blockDim.x + threadIdx.x;  // over NTOK*DI
    int d = idx & (DI-1);
    int t = (idx >> 10) & (LL-1);
    int b = idx >> 21;
    const float* xz = g_xz[dir];
    float acc = bias[d];
    #pragma unroll
    for (int j=0;j<4;j++){
        int tt = (dir==0) ? (t-3+j) : (t+3-j);
        if (tt>=0 && tt<LL)
            acc = fmaf(w[d*4+j], xz[((b*LL+tt)*2*DI) + d], acc);
    }
    g_xi[dir][idx] = acc / (1.f + __expf(-acc));   // silu
}

// ---------------- selective scan: 1 warp = 2 channels, 16 lanes = DSTATE ---
__global__ void scan_kernel(const float* __restrict__ A_log,
                            const float* __restrict__ Dp, int dir){
    int gw   = (blockIdx.x*blockDim.x + threadIdx.x) >> 5;  // 0..1023
    int lane = threadIdx.x & 31;
    int n    = lane & 15;
    int half = lane >> 4;
    int b    = gw >> 9;
    int d    = (gw & 511)*2 + half;
    float a  = -expf(A_log[d*DS + n]);
    float Dv = Dp[d];
    const float* xdbl = g_xdbl[dir];
    const float* dtp  = g_dt[dir];
    const float* xip  = g_xi[dir];
    const float* xzp  = g_xz[dir];
    float* yp = g_y[dir];
    float h = 0.f;
    int t0 = (dir==0) ? 0 : LL-1;
    int st = (dir==0) ? 1 : -1;
    for (int s=0; s<LL; s++){
        int t = t0 + s*st;
        int tok = b*LL + t;
        float Bt  = xdbl[tok*64 + 32 + n];
        float Ct  = xdbl[tok*64 + 48 + n];
        float dtv = dtp[tok*DI + d];
        float xiv = xip[tok*DI + d];
        float dA  = __expf(dtv * a);
        h = fmaf(dA, h, dtv*Bt*xiv);
        float p = h*Ct;
        p += __shfl_xor_sync(0xffffffffu, p, 8);
        p += __shfl_xor_sync(0xffffffffu, p, 4);
        p += __shfl_xor_sync(0xffffffffu, p, 2);
        p += __shfl_xor_sync(0xffffffffu, p, 1);
        if (n==0){
            float zv = xzp[tok*2*DI + DI + d];
            float yv = p + xiv*Dv;
            yv *= zv / (1.f + __expf(-zv));       // * silu(z)
            yp[tok*DI + d] = yv;
        }
    }
}

// ---------------- host launcher --------------------------------------------
extern "C" void kernel_launch(void* const* d_in, const int* in_sizes, int n_in,
                              void* d_out, int out_size){
    const float* x      = (const float*)d_in[0];
    const float* ln_g   = (const float*)d_in[1];
    const float* ln_b   = (const float*)d_in[2];
    const float* proj_w = (const float*)d_in[3];
    const float* proj_b = (const float*)d_in[4];
    const float* P[2][9];
    for (int dir=0; dir<2; dir++)
        for (int i=0;i<9;i++)
            P[dir][i] = (const float*)d_in[5 + dir*9 + i];
    // P[dir]: 0 in_w, 1 conv_w, 2 conv_b, 3 xproj_w, 4 dt_w, 5 dt_b,
    //         6 A_log, 7 D, 8 out_w

    float *p_xn,*p_xz,*p_xi,*p_xdbl,*p_dt,*p_y,*p_yc;
    cudaGetSymbolAddress((void**)&p_xn,   g_xn);
    cudaGetSymbolAddress((void**)&p_xz,   g_xz);
    cudaGetSymbolAddress((void**)&p_xi,   g_xi);
    cudaGetSymbolAddress((void**)&p_xdbl, g_xdbl);
    cudaGetSymbolAddress((void**)&p_dt,   g_dt);
    cudaGetSymbolAddress((void**)&p_y,    g_y);
    cudaGetSymbolAddress((void**)&p_yc,   g_yc);

    // 1. layernorm
    ln_kernel<<<NTOK, 256>>>(x, ln_g, ln_b);

    // 2. in-projection: xz = xn @ in_w   (4096 x 2048, K=512), per direction
    for (int dir=0;dir<2;dir++)
        sgemm<<<dim3(2*DI/128, NTOK/128), 256>>>(
            p_xn, DM, P[dir][0], 2*DI,
            p_xz + (long)dir*NTOK*2*DI, 2*DI, 2*DI, DM, nullptr, nullptr, 0, 0);

    // 3. depthwise conv + SiLU
    for (int dir=0;dir<2;dir++)
        conv_kernel<<<NTOK*DI/256, 256>>>(P[dir][1], P[dir][2], dir);

    // 4. x_proj: xdbl = xi @ xproj_w   (4096 x 64, K=1024)
    for (int dir=0;dir<2;dir++)
        sgemm<<<dim3(1, NTOK/128), 256>>>(
            p_xi + (long)dir*NTOK*DI, DI, P[dir][3], 64,
            p_xdbl + (long)dir*NTOK*64, 64, 64, DI, nullptr, nullptr, 0, 0);

    // 5. dt = softplus(xdbl[:, :32] @ dt_w + dt_b)   (4096 x 1024, K=32)
    for (int dir=0;dir<2;dir++)
        sgemm<<<dim3(DI/128, NTOK/128), 256>>>(
            p_xdbl + (long)dir*NTOK*64, 64, P[dir][4], DI,
            p_dt + (long)dir*NTOK*DI, DI, DI, 32, P[dir][5], nullptr, 0, 2);

    // 6. selective scan (+ xi*D, * silu(z))
    for (int dir=0;dir<2;dir++)
        scan_kernel<<<128, 256>>>(P[dir][6], P[dir][7], dir);

    // 7. ycomb = y_f @ f_out_w + y_b @ b_out_w   (4096 x 512, K=1024)
    sgemm<<<dim3(DM/128, NTOK/128), 256>>>(
        p_y, DI, P[0][8], DM, p_yc, DM, DM, DI, nullptr, nullptr, 0, 0);
    sgemm<<<dim3(DM/128, NTOK/128), 256>>>(
        p_y + (long)NTOK*DI, DI, P[1][8], DM, p_yc, DM, DM, DI, nullptr, nullptr, 0, 1);

    // 8. out = ycomb @ proj_w + proj_b + x   (4096 x 512, K=512)
    sgemm<<<dim3(DM/128, NTOK/128), 256>>>(
        p_yc, DM, proj_w, DM, (float*)d_out, DM, DM, DM, proj_b, x, DM, 3);
}

// round 2
// speedup vs baseline: 2.1376x; 2.1376x over previous
#include <cuda_runtime.h>
#include <cuda_bf16.h>
#include <math.h>

#define BB 2
#define LL 2048
#define DM 512
#define DI 1024
#define DS 16
#define NTOK (BB*LL)   // 4096

typedef unsigned short bf16raw;

static __device__ __forceinline__ bf16raw f2b(float x){
    __nv_bfloat16 h = __float2bfloat16_rn(x);
    return *reinterpret_cast<bf16raw*>(&h);
}

// ---------------- scratch -------------------------------------------------
__device__ float   g_xz[2][NTOK*2*DI];       // in-proj out (xi|z)  128 MB
__device__ float   g_xi[2][NTOK*DI];         // conv+silu out (fp32 for scan)
__device__ float   g_xdbl[2][NTOK*64];       // x_proj out (fp32 for scan B/C)
__device__ float   g_dt[2][NTOK*DI];         // softplus(dt)
__device__ float   g_dtb[2][DI];             // dt bias packed
__device__ bf16raw g_xn_bf[NTOK*DM];         // LN out, bf16 (GEMM1 A)
__device__ bf16raw g_xi_bf[2][NTOK*DI];      // conv out bf16 (GEMM2 A)
__device__ bf16raw g_xdbl_bf[2][NTOK*64];    // GEMM3 A
__device__ bf16raw g_ycat_bf[NTOK*2*DI];     // [tok][dir*DI+d]  (GEMM4 A)
__device__ bf16raw g_yc_bf[NTOK*DM];         // GEMM5 A
// bf16 weights
__device__ bf16raw g_w_in[2][DM*2*DI];
__device__ bf16raw g_w_xp[2][DI*64];
__device__ bf16raw g_w_dt[2][32*DI];
__device__ bf16raw g_w_cat[2*DI*DM];         // [f_out_w ; b_out_w]
__device__ bf16raw g_w_pj[DM*DM];

// ---------------- fp32 -> bf16 conversion ---------------------------------
__global__ void cvt_kernel(const float* __restrict__ s, bf16raw* __restrict__ d, int n){
    int i = (blockIdx.x*blockDim.x + threadIdx.x)*4;
    if (i < n){
        float4 v = *(const float4*)(s + i);
        d[i+0]=f2b(v.x); d[i+1]=f2b(v.y); d[i+2]=f2b(v.z); d[i+3]=f2b(v.w);
    }
}

__global__ void pack_dtb_kernel(const float* __restrict__ f, const float* __restrict__ b){
    int i = blockIdx.x*blockDim.x + threadIdx.x;
    if (i < DI)            g_dtb[0][i]    = f[i];
    else if (i < 2*DI)     g_dtb[1][i-DI] = b[i-DI];
}

// ---------------- layernorm (writes bf16) ---------------------------------
__global__ void ln_kernel(const float* __restrict__ x,
                          const float* __restrict__ g,
                          const float* __restrict__ b) {
    int row = blockIdx.x;
    const float* xr = x + (long)row*DM;
    int tid = threadIdx.x;
    float v0 = xr[tid], v1 = xr[tid+256];
    __shared__ float s1[256], s2[256];
    s1[tid] = v0+v1; s2[tid] = v0*v0+v1*v1;
    __syncthreads();
    for (int o=128;o>0;o>>=1){
        if (tid<o){ s1[tid]+=s1[tid+o]; s2[tid]+=s2[tid+o]; }
        __syncthreads();
    }
    float mu = s1[0]*(1.0f/DM);
    float var = s2[0]*(1.0f/DM) - mu*mu;
    float rs = rsqrtf(var + 1e-5f);
    g_xn_bf[(long)row*DM+tid]     = f2b((v0-mu)*rs*g[tid]     + b[tid]);
    g_xn_bf[(long)row*DM+tid+256] = f2b((v1-mu)*rs*g[tid+256] + b[tid+256]);
}

// ---------------- bf16 tensor-core GEMM 128x128x32 -------------------------
// C[M,N] = A[M,K] @ B[K,N], A/B bf16 row-major, fp32 accumulate.
// epi: 0 plain, 2 softplus(v+bias), 3 v+bias+res. Optional bf16 shadow Ob.
__global__ __launch_bounds__(256) void hgemm(
    const bf16raw* __restrict__ Ag, long sA, int lda,
    const bf16raw* __restrict__ Bg, long sB, int ldb,
    float* __restrict__ Cg, long sC, int ldc,
    bf16raw* __restrict__ Obg, long sO,
    int N, int K,
    const float* __restrict__ biasg, long sbias,
    const float* __restrict__ res, int ldres,
    int epi)
{
    const bf16raw* A = Ag + sA*blockIdx.z;
    const bf16raw* B = Bg + sB*blockIdx.z;
    float* C   = Cg  ? Cg  + sC*blockIdx.z : nullptr;
    bf16raw* Ob = Obg ? Obg + sO*blockIdx.z : nullptr;
    const float* bias = biasg ? biasg + sbias*blockIdx.z : nullptr;

    __shared__ bf16raw As[2][128*40];   // 32 halves data + 8 pad per row
    __shared__ bf16raw Bs[2][32*128];   // 16B-chunk XOR swizzle

    int tid = threadIdx.x;
    int lane = tid & 31, wid = tid >> 5;
    int warp_m = wid & 3, warp_n = wid >> 2;     // 4 x 2 warps
    int bm = blockIdx.y*128, bn = blockIdx.x*128;

    float acc[2][8][4];
    #pragma unroll
    for (int a=0;a<2;a++) for (int b2=0;b2<8;b2++) for (int c=0;c<4;c++) acc[a][b2][c]=0.f;

    int KT = K >> 5;

    // ---- tile loader (cp.async) ----
    auto loadTile = [&](int kt, int buf){
        int k0 = kt*32;
        #pragma unroll
        for (int i=0;i<2;i++){                    // A: 512 16B chunks
            int q = tid + i*256;
            int r = q>>2, c = q&3;
            const bf16raw* src = A + (long)(bm+r)*lda + k0 + c*8;
            unsigned sa = (unsigned)__cvta_generic_to_shared(&As[buf][r*40 + c*8]);
            asm volatile("cp.async.cg.shared.global [%0], [%1], 16;\n" :: "r"(sa), "l"(src));
        }
        #pragma unroll
        for (int i=0;i<2;i++){                    // B: 512 16B chunks
            int q = tid + i*256;
            int r = q>>4, c = q&15;
            int gcol = bn + c*8;
            const bf16raw* src = B + (long)(k0+r)*ldb + gcol;
            unsigned sa = (unsigned)__cvta_generic_to_shared(&Bs[buf][r*128 + ((c ^ (r&7))*8)]);
            int sz = (gcol < N) ? 16 : 0;
            asm volatile("cp.async.cg.shared.global [%0], [%1], 16, %2;\n" :: "r"(sa), "l"(src), "r"(sz));
        }
    };

    loadTile(0, 0);
    asm volatile("cp.async.commit_group;\n" ::: "memory");

    for (int kt=0; kt<KT; kt++){
        if (kt+1 < KT) loadTile(kt+1, (kt+1)&1);
        asm volatile("cp.async.commit_group;\n" ::: "memory");
        asm volatile("cp.async.wait_group 1;\n" ::: "memory");
        __syncthreads();
        int buf = kt & 1;

        #pragma unroll
        for (int ks=0; ks<2; ks++){
            unsigned af[2][4];
            #pragma unroll
            for (int mt=0; mt<2; mt++){
                int row = warp_m*32 + mt*16 + (lane&15);
                int chunk = ks*2 + (lane>>4);
                unsigned addr = (unsigned)__cvta_generic_to_shared(&As[buf][row*40 + chunk*8]);
                asm volatile("ldmatrix.sync.aligned.m8n8.x4.shared.b16 {%0,%1,%2,%3}, [%4];"
                    : "=r"(af[mt][0]),"=r"(af[mt][1]),"=r"(af[mt][2]),"=r"(af[mt][3]) : "r"(addr));
            }
            unsigned bfm[8][2];
            #pragma unroll
            for (int jn=0; jn<4; jn++){
                int row = ks*16 + (lane&15);
                int c = warp_n*8 + jn*2 + (lane>>4);
                unsigned addr = (unsigned)__cvta_generic_to_shared(&Bs[buf][row*128 + ((c ^ (row&7))*8)]);
                unsigned r0,r1,r2,r3;
                asm volatile("ldmatrix.sync.aligned.m8n8.x4.trans.shared.b16 {%0,%1,%2,%3}, [%4];"
                    : "=r"(r0),"=r"(r1),"=r"(r2),"=r"(r3) : "r"(addr));
                bfm[jn*2][0]=r0;   bfm[jn*2][1]=r1;
                bfm[jn*2+1][0]=r2; bfm[jn*2+1][1]=r3;
            }
            #pragma unroll
            for (int mt=0; mt<2; mt++)
                #pragma unroll
                for (int nt=0; nt<8; nt++){
                    asm volatile("mma.sync.aligned.m16n8k16.row.col.f32.bf16.bf16.f32 "
                        "{%0,%1,%2,%3}, {%4,%5,%6,%7}, {%8,%9}, {%0,%1,%2,%3};"
                        : "+f"(acc[mt][nt][0]),"+f"(acc[mt][nt][1]),
                          "+f"(acc[mt][nt][2]),"+f"(acc[mt][nt][3])
                        : "r"(af[mt][0]),"r"(af[mt][1]),"r"(af[mt][2]),"r"(af[mt][3]),
                          "r"(bfm[nt][0]),"r"(bfm[nt][1]));
                }
        }
        __syncthreads();
    }

    // ---- epilogue ----
    #pragma unroll
    for (int mt=0; mt<2; mt++){
        #pragma unroll
        for (int i2=0; i2<2; i2++){
            long r = bm + warp_m*32 + mt*16 + (lane>>2) + i2*8;
            #pragma unroll
            for (int nt=0; nt<8; nt++){
                int cbase = bn + warp_n*64 + nt*8 + (lane&3)*2;
                #pragma unroll
                for (int j=0; j<2; j++){
                    int c = cbase + j;
                    if (c >= N) continue;
                    float v = acc[mt][nt][i2*2+j];
                    if (epi==2){ v += bias[c]; v = (v>20.f)? v : log1pf(expf(v)); }
                    else if (epi==3){ v += bias[c] + res[r*ldres + c]; }
                    if (C)  C[r*ldc + c] = v;
                    if (Ob) Ob[r*ldc + c] = f2b(v);
                }
            }
        }
    }
}

// ---------------- depthwise conv + SiLU (both dirs via grid.z) -------------
__global__ void conv_kernel(const float* __restrict__ wf, const float* __restrict__ biasf,
                            const float* __restrict__ wb, const float* __restrict__ biasb){
    int dir = blockIdx.z;
    const float* w    = dir ? wb : wf;
    const float* bias = dir ? biasb : biasf;
    int idx = blockIdx.x*blockDim.x + threadIdx.x;      // over NTOK*DI
    int d = idx & (DI-1);
    int t = (idx >> 10) & (LL-1);
    int b = idx >> 21;
    const float* xz = g_xz[dir];
    float acc = bias[d];
    #pragma unroll
    for (int j=0;j<4;j++){
        int tt = (dir==0) ? (t-3+j) : (t+3-j);
        if (tt>=0 && tt<LL)
            acc = fmaf(w[d*4+j], xz[((long)(b*LL+tt)*2*DI) + d], acc);
    }
    float s = acc / (1.f + __expf(-acc));
    g_xi[dir][idx]    = s;
    g_xi_bf[dir][idx] = f2b(s);
}

// ---------------- selective scan (both dirs via grid.z) --------------------
__global__ void scan_kernel(const float* __restrict__ fA, const float* __restrict__ fD,
                            const float* __restrict__ bA, const float* __restrict__ bD){
    int dir = blockIdx.z;
    const float* A_log = dir ? bA : fA;
    const float* Dp    = dir ? bD : fD;
    int gw   = (blockIdx.x*blockDim.x + threadIdx.x) >> 5;  // 0..1023
    int lane = threadIdx.x & 31;
    int n    = lane & 15;
    int half = lane >> 4;
    int b    = gw >> 9;
    int d    = (gw & 511)*2 + half;
    float a  = -expf(A_log[d*DS + n]);
    float Dv = Dp[d];
    const float* xdbl = g_xdbl[dir];
    const float* dtp  = g_dt[dir];
    const float* xip  = g_xi[dir];
    const float* xzp  = g_xz[dir];
    float h = 0.f;
    int t0 = (dir==0) ? 0 : LL-1;
    int st = (dir==0) ? 1 : -1;
    for (int s=0; s<LL; s++){
        int t = t0 + s*st;
        int tok = b*LL + t;
        float Bt  = xdbl[tok*64 + 32 + n];
        float Ct  = xdbl[tok*64 + 48 + n];
        float dtv = dtp[(long)tok*DI + d];
        float xiv = xip[(long)tok*DI + d];
        float dA  = __expf(dtv * a);
        h = fmaf(dA, h, dtv*Bt*xiv);
        float p = h*Ct;
        p += __shfl_xor_sync(0xffffffffu, p, 8);
        p += __shfl_xor_sync(0xffffffffu, p, 4);
        p += __shfl_xor_sync(0xffffffffu, p, 2);
        p += __shfl_xor_sync(0xffffffffu, p, 1);
        if (n==0){
            float zv = xzp[(long)tok*2*DI + DI + d];
            float yv = p + xiv*Dv;
            yv *= zv / (1.f + __expf(-zv));
            g_ycat_bf[(long)tok*2*DI + dir*DI + d] = f2b(yv);
        }
    }
}

// ---------------- host launcher --------------------------------------------
extern "C" void kernel_launch(void* const* d_in, const int* in_sizes, int n_in,
                              void* d_out, int out_size){
    const float* x      = (const float*)d_in[0];
    const float* ln_g   = (const float*)d_in[1];
    const float* ln_b   = (const float*)d_in[2];
    const float* proj_w = (const float*)d_in[3];
    const float* proj_b = (const float*)d_in[4];
    const float* P[2][9];
    for (int dir=0; dir<2; dir++)
        for (int i=0;i<9;i++)
            P[dir][i] = (const float*)d_in[5 + dir*9 + i];
    // P[dir]: 0 in_w, 1 conv_w, 2 conv_b, 3 xproj_w, 4 dt_w, 5 dt_b,
    //         6 A_log, 7 D, 8 out_w

    float   *p_xz,*p_xdbl,*p_dt,*p_dtb;
    bf16raw *p_xn,*p_xib,*p_xdblb,*p_ycat,*p_ycb;
    bf16raw *w_in,*w_xp,*w_dt,*w_cat,*w_pj;
    cudaGetSymbolAddress((void**)&p_xz,    g_xz);
    cudaGetSymbolAddress((void**)&p_xdbl,  g_xdbl);
    cudaGetSymbolAddress((void**)&p_dt,    g_dt);
    cudaGetSymbolAddress((void**)&p_dtb,   g_dtb);
    cudaGetSymbolAddress((void**)&p_xn,    g_xn_bf);
    cudaGetSymbolAddress((void**)&p_xib,   g_xi_bf);
    cudaGetSymbolAddress((void**)&p_xdblb, g_xdbl_bf);
    cudaGetSymbolAddress((void**)&p_ycat,  g_ycat_bf);
    cudaGetSymbolAddress((void**)&p_ycb,   g_yc_bf);
    cudaGetSymbolAddress((void**)&w_in,    g_w_in);
    cudaGetSymbolAddress((void**)&w_xp,    g_w_xp);
    cudaGetSymbolAddress((void**)&w_dt,    g_w_dt);
    cudaGetSymbolAddress((void**)&w_cat,   g_w_cat);
    cudaGetSymbolAddress((void**)&w_pj,    g_w_pj);

    auto cvt = [&](const float* s, bf16raw* d, int n){
        cvt_kernel<<<(n/4+255)/256, 256>>>(s, d, n);
    };

    // 0. weight conversions (independent, tiny)
    cvt(P[0][0], w_in,              DM*2*DI);
    cvt(P[1][0], w_in + DM*2*DI,    DM*2*DI);
    cvt(P[0][3], w_xp,              DI*64);
    cvt(P[1][3], w_xp + DI*64,      DI*64);
    cvt(P[0][4], w_dt,              32*DI);
    cvt(P[1][4], w_dt + 32*DI,      32*DI);
    cvt(P[0][8], w_cat,             DI*DM);
    cvt(P[1][8], w_cat + DI*DM,     DI*DM);
    cvt(proj_w,  w_pj,              DM*DM);
    pack_dtb_kernel<<<(2*DI+255)/256, 256>>>(P[0][5], P[1][5]);

    // 1. layernorm -> bf16
    ln_kernel<<<NTOK, 256>>>(x, ln_g, ln_b);

    // 2. in-proj: xz = xn @ in_w  (4096 x 2048, K=512), dirs batched in z
    hgemm<<<dim3(2*DI/128, NTOK/128, 2), 256>>>(
        p_xn, 0, DM,
        w_in, (long)DM*2*DI, 2*DI,
        p_xz, (long)NTOK*2*DI, 2*DI,
        nullptr, 0,
        2*DI, DM, nullptr, 0, nullptr, 0, 0);

    // 3. conv + SiLU
    conv_kernel<<<dim3(NTOK*DI/256,1,2), 256>>>(P[0][1], P[0][2], P[1][1], P[1][2]);

    // 4. x_proj: xdbl = xi @ xproj_w  (4096 x 64, K=1024) + bf16 shadow
    hgemm<<<dim3(1, NTOK/128, 2), 256>>>(
        p_xib, (long)NTOK*DI, DI,
        w_xp,  (long)DI*64,   64,
        p_xdbl,(long)NTOK*64, 64,
        p_xdblb,(long)NTOK*64,
        64, DI, nullptr, 0, nullptr, 0, 0);

    // 5. dt = softplus(xdbl[:, :32] @ dt_w + dt_b)  (4096 x 1024, K=32)
    hgemm<<<dim3(DI/128, NTOK/128, 2), 256>>>(
        p_xdblb,(long)NTOK*64, 64,
        w_dt,   (long)32*DI,   DI,
        p_dt,   (long)NTOK*DI, DI,
        nullptr, 0,
        DI, 32, p_dtb, DI, nullptr, 0, 2);

    // 6. selective scan -> ycat bf16
    scan_kernel<<<dim3(128,1,2), 256>>>(P[0][6], P[0][7], P[1][6], P[1][7]);

    // 7. yc = [y_f|y_b] @ [f_out_w; b_out_w]  (4096 x 512, K=2048) -> bf16
    hgemm<<<dim3(DM/128, NTOK/128, 1), 256>>>(
        p_ycat, 0, 2*DI,
        w_cat,  0, DM,
        nullptr, 0, DM,
        p_ycb, 0,
        DM, 2*DI, nullptr, 0, nullptr, 0, 0);

    // 8. out = yc @ proj_w + proj_b + x  (4096 x 512, K=512)
    hgemm<<<dim3(DM/128, NTOK/128, 1), 256>>>(
        p_ycb, 0, DM,
        w_pj,  0, DM,
        (float*)d_out, 0, DM,
        nullptr, 0,
        DM, DM, proj_b, 0, x, DM, 3);
}

// round 3
// speedup vs baseline: 8.1330x; 3.8047x over previous
#include <cuda_runtime.h>
#include <cuda_bf16.h>
#include <math.h>

#define BB 2
#define LL 2048
#define DM 512
#define DI 1024
#define DS 16
#define NTOK (BB*LL)   // 4096
#define TCHUNK 64
#define CH 16

typedef unsigned short bf16raw;

static __device__ __forceinline__ bf16raw f2b(float x){
    __nv_bfloat16 h = __float2bfloat16_rn(x);
    return *reinterpret_cast<bf16raw*>(&h);
}
static __device__ __forceinline__ void cp16(void* dst, const void* src){
    unsigned sa = (unsigned)__cvta_generic_to_shared(dst);
    asm volatile("cp.async.cg.shared.global [%0], [%1], 16;" :: "r"(sa), "l"(src));
}

// ---------------- scratch -------------------------------------------------
__device__ float   g_xz[2][NTOK*2*DI];       // in-proj out (xi|z)
__device__ float   g_xi[2][NTOK*DI];         // conv+silu out (fp32 for scan)
__device__ float   g_xdbl[2][NTOK*64];       // x_proj out (fp32 for scan B/C)
__device__ float   g_dt[2][NTOK*DI];         // softplus(dt)
__device__ float   g_dtb[2][DI];             // dt bias packed
__device__ bf16raw g_xn_bf[NTOK*DM];         // LN out, bf16 (GEMM1 A)
__device__ bf16raw g_xi_bf[2][NTOK*DI];      // conv out bf16 (GEMM2 A)
__device__ bf16raw g_xdbl_bf[2][NTOK*64];    // GEMM3 A
__device__ bf16raw g_ycat_bf[NTOK*2*DI];     // [tok][dir*DI+d]  (GEMM4 A)
__device__ bf16raw g_yc_bf[NTOK*DM];         // GEMM5 A
// bf16 weights
__device__ bf16raw g_w_in[2][DM*2*DI];
__device__ bf16raw g_w_xp[2][DI*64];
__device__ bf16raw g_w_dt[2][32*DI];
__device__ bf16raw g_w_cat[2*DI*DM];
__device__ bf16raw g_w_pj[DM*DM];

// ---------------- fused fp32 -> bf16 weight conversion ---------------------
struct CvtArgs { const float* s[9]; bf16raw* d[9]; int off[10]; };

__global__ void cvt_all_kernel(CvtArgs a, int total4){
    int i = blockIdx.x*blockDim.x + threadIdx.x;   // float4 index
    if (i >= total4) return;
    int seg = 0;
    while (i >= a.off[seg+1]) seg++;
    int j = (i - a.off[seg])*4;
    float4 v = *(const float4*)(a.s[seg] + j);
    bf16raw* d = a.d[seg] + j;
    d[0]=f2b(v.x); d[1]=f2b(v.y); d[2]=f2b(v.z); d[3]=f2b(v.w);
}

__global__ void pack_dtb_kernel(const float* __restrict__ f, const float* __restrict__ b){
    int i = blockIdx.x*blockDim.x + threadIdx.x;
    if (i < DI)            g_dtb[0][i]    = f[i];
    else if (i < 2*DI)     g_dtb[1][i-DI] = b[i-DI];
}

// ---------------- layernorm (writes bf16) ---------------------------------
__global__ void ln_kernel(const float* __restrict__ x,
                          const float* __restrict__ g,
                          const float* __restrict__ b) {
    int row = blockIdx.x;
    const float* xr = x + (long)row*DM;
    int tid = threadIdx.x;
    float v0 = xr[tid], v1 = xr[tid+256];
    __shared__ float s1[256], s2[256];
    s1[tid] = v0+v1; s2[tid] = v0*v0+v1*v1;
    __syncthreads();
    for (int o=128;o>0;o>>=1){
        if (tid<o){ s1[tid]+=s1[tid+o]; s2[tid]+=s2[tid+o]; }
        __syncthreads();
    }
    float mu = s1[0]*(1.0f/DM);
    float var = s2[0]*(1.0f/DM) - mu*mu;
    float rs = rsqrtf(var + 1e-5f);
    g_xn_bf[(long)row*DM+tid]     = f2b((v0-mu)*rs*g[tid]     + b[tid]);
    g_xn_bf[(long)row*DM+tid+256] = f2b((v1-mu)*rs*g[tid+256] + b[tid+256]);
}

// ---------------- bf16 tensor-core GEMM 128x128x32 -------------------------
__global__ __launch_bounds__(256) void hgemm(
    const bf16raw* __restrict__ Ag, long sA, int lda,
    const bf16raw* __restrict__ Bg, long sB, int ldb,
    float* __restrict__ Cg, long sC, int ldc,
    bf16raw* __restrict__ Obg, long sO,
    int N, int K,
    const float* __restrict__ biasg, long sbias,
    const float* __restrict__ res, int ldres,
    int epi)
{
    const bf16raw* A = Ag + sA*blockIdx.z;
    const bf16raw* B = Bg + sB*blockIdx.z;
    float* C   = Cg  ? Cg  + sC*blockIdx.z : nullptr;
    bf16raw* Ob = Obg ? Obg + sO*blockIdx.z : nullptr;
    const float* bias = biasg ? biasg + sbias*blockIdx.z : nullptr;

    __shared__ bf16raw As[2][128*40];
    __shared__ bf16raw Bs[2][32*128];

    int tid = threadIdx.x;
    int lane = tid & 31, wid = tid >> 5;
    int warp_m = wid & 3, warp_n = wid >> 2;
    int bm = blockIdx.y*128, bn = blockIdx.x*128;

    float acc[2][8][4];
    #pragma unroll
    for (int a=0;a<2;a++) for (int b2=0;b2<8;b2++) for (int c=0;c<4;c++) acc[a][b2][c]=0.f;

    int KT = K >> 5;

    auto loadTile = [&](int kt, int buf){
        int k0 = kt*32;
        #pragma unroll
        for (int i=0;i<2;i++){
            int q = tid + i*256;
            int r = q>>2, c = q&3;
            const bf16raw* src = A + (long)(bm+r)*lda + k0 + c*8;
            unsigned sa = (unsigned)__cvta_generic_to_shared(&As[buf][r*40 + c*8]);
            asm volatile("cp.async.cg.shared.global [%0], [%1], 16;\n" :: "r"(sa), "l"(src));
        }
        #pragma unroll
        for (int i=0;i<2;i++){
            int q = tid + i*256;
            int r = q>>4, c = q&15;
            int gcol = bn + c*8;
            const bf16raw* src = B + (long)(k0+r)*ldb + gcol;
            unsigned sa = (unsigned)__cvta_generic_to_shared(&Bs[buf][r*128 + ((c ^ (r&7))*8)]);
            int sz = (gcol < N) ? 16 : 0;
            asm volatile("cp.async.cg.shared.global [%0], [%1], 16, %2;\n" :: "r"(sa), "l"(src), "r"(sz));
        }
    };

    loadTile(0, 0);
    asm volatile("cp.async.commit_group;\n" ::: "memory");

    for (int kt=0; kt<KT; kt++){
        if (kt+1 < KT) loadTile(kt+1, (kt+1)&1);
        asm volatile("cp.async.commit_group;\n" ::: "memory");
        asm volatile("cp.async.wait_group 1;\n" ::: "memory");
        __syncthreads();
        int buf = kt & 1;

        #pragma unroll
        for (int ks=0; ks<2; ks++){
            unsigned af[2][4];
            #pragma unroll
            for (int mt=0; mt<2; mt++){
                int row = warp_m*32 + mt*16 + (lane&15);
                int chunk = ks*2 + (lane>>4);
                unsigned addr = (unsigned)__cvta_generic_to_shared(&As[buf][row*40 + chunk*8]);
                asm volatile("ldmatrix.sync.aligned.m8n8.x4.shared.b16 {%0,%1,%2,%3}, [%4];"
                    : "=r"(af[mt][0]),"=r"(af[mt][1]),"=r"(af[mt][2]),"=r"(af[mt][3]) : "r"(addr));
            }
            unsigned bfm[8][2];
            #pragma unroll
            for (int jn=0; jn<4; jn++){
                int row = ks*16 + (lane&15);
                int c = warp_n*8 + jn*2 + (lane>>4);
                unsigned addr = (unsigned)__cvta_generic_to_shared(&Bs[buf][row*128 + ((c ^ (row&7))*8)]);
                unsigned r0,r1,r2,r3;
                asm volatile("ldmatrix.sync.aligned.m8n8.x4.trans.shared.b16 {%0,%1,%2,%3}, [%4];"
                    : "=r"(r0),"=r"(r1),"=r"(r2),"=r"(r3) : "r"(addr));
                bfm[jn*2][0]=r0;   bfm[jn*2][1]=r1;
                bfm[jn*2+1][0]=r2; bfm[jn*2+1][1]=r3;
            }
            #pragma unroll
            for (int mt=0; mt<2; mt++)
                #pragma unroll
                for (int nt=0; nt<8; nt++){
                    asm volatile("mma.sync.aligned.m16n8k16.row.col.f32.bf16.bf16.f32 "
                        "{%0,%1,%2,%3}, {%4,%5,%6,%7}, {%8,%9}, {%0,%1,%2,%3};"
                        : "+f"(acc[mt][nt][0]),"+f"(acc[mt][nt][1]),
                          "+f"(acc[mt][nt][2]),"+f"(acc[mt][nt][3])
                        : "r"(af[mt][0]),"r"(af[mt][1]),"r"(af[mt][2]),"r"(af[mt][3]),
                          "r"(bfm[nt][0]),"r"(bfm[nt][1]));
                }
        }
        __syncthreads();
    }

    #pragma unroll
    for (int mt=0; mt<2; mt++){
        #pragma unroll
        for (int i2=0; i2<2; i2++){
            long r = bm + warp_m*32 + mt*16 + (lane>>2) + i2*8;
            #pragma unroll
            for (int nt=0; nt<8; nt++){
                int cbase = bn + warp_n*64 + nt*8 + (lane&3)*2;
                #pragma unroll
                for (int j=0; j<2; j++){
                    int c = cbase + j;
                    if (c >= N) continue;
                    float v = acc[mt][nt][i2*2+j];
                    if (epi==2){ v += bias[c]; v = (v>20.f)? v : log1pf(expf(v)); }
                    else if (epi==3){ v += bias[c] + res[r*ldres + c]; }
                    if (C)  C[r*ldc + c] = v;
                    if (Ob) Ob[r*ldc + c] = f2b(v);
                }
            }
        }
    }
}

// ---------------- depthwise conv + SiLU (both dirs via grid.z) -------------
__global__ void conv_kernel(const float* __restrict__ wf, const float* __restrict__ biasf,
                            const float* __restrict__ wb, const float* __restrict__ biasb){
    int dir = blockIdx.z;
    const float* w    = dir ? wb : wf;
    const float* bias = dir ? biasb : biasf;
    int idx = blockIdx.x*blockDim.x + threadIdx.x;
    int d = idx & (DI-1);
    int t = (idx >> 10) & (LL-1);
    int b = idx >> 21;
    const float* xz = g_xz[dir];
    float acc = bias[d];
    #pragma unroll
    for (int j=0;j<4;j++){
        int tt = (dir==0) ? (t-3+j) : (t+3-j);
        if (tt>=0 && tt<LL)
            acc = fmaf(w[d*4+j], xz[((long)(b*LL+tt)*2*DI) + d], acc);
    }
    float s = acc / (1.f + __expf(-acc));
    g_xi[dir][idx]    = s;
    g_xi_bf[dir][idx] = f2b(s);
}

// ---------------- selective scan: smem-staged, cp.async double-buffered ----
// block = 256 threads, owns CH=16 channels of one (batch, dir).
// grid = (DI/CH=64, BB, 2)
__global__ __launch_bounds__(256) void scan_kernel(
    const float* __restrict__ fA, const float* __restrict__ fD,
    const float* __restrict__ bA, const float* __restrict__ bD)
{
    int dir = blockIdx.z;
    int b   = blockIdx.y;
    int d0  = blockIdx.x * CH;
    const float* A_log = dir ? bA : fA;
    const float* Dp    = dir ? bD : fD;

    __shared__ __align__(16) float s_dt[2][TCHUNK][CH];
    __shared__ __align__(16) float s_xi[2][TCHUNK][CH];
    __shared__ __align__(16) float s_z [2][TCHUNK][CH];
    __shared__ __align__(16) float s_bc[2][TCHUNK][32];
    __shared__ __align__(8)  bf16raw s_y[2][TCHUNK][CH];

    int tid  = threadIdx.x;
    int wid  = tid >> 5, lane = tid & 31;
    int half = lane >> 4, n = lane & 15;
    int dl   = wid*2 + half;
    int d    = d0 + dl;

    float a  = -expf(A_log[d*DS + n]);
    float Dv = Dp[d];

    const float* dtp = g_dt[dir];
    const float* xip = g_xi[dir];
    const float* xzp = g_xz[dir];
    const float* bcp = g_xdbl[dir];

    const int NCH = LL / TCHUNK;   // 32 chunks

    auto loadChunk = [&](int c, int buf){
        {   // dt / xi / z : 64 rows x 16 floats, 4 x 16B per row
            int row = tid >> 2, seg = tid & 3;
            int trow = (dir==0) ? c*TCHUNK+row : (LL-1) - (c*TCHUNK+row);
            long tok = (long)b*LL + trow;
            cp16(&s_dt[buf][row][seg*4], dtp + tok*DI + d0 + seg*4);
            cp16(&s_xi[buf][row][seg*4], xip + tok*DI + d0 + seg*4);
            cp16(&s_z [buf][row][seg*4], xzp + tok*2*DI + DI + d0 + seg*4);
        }
        #pragma unroll
        for (int i=0;i<2;i++){   // B|C : 64 rows x 32 floats, 8 x 16B per row
            int q = tid + i*256;
            int row = q >> 3, seg = q & 7;
            int trow = (dir==0) ? c*TCHUNK+row : (LL-1) - (c*TCHUNK+row);
            long tok = (long)b*LL + trow;
            cp16(&s_bc[buf][row][seg*4], bcp + tok*64 + 32 + seg*4);
        }
    };

    float h = 0.f;
    loadChunk(0, 0);
    asm volatile("cp.async.commit_group;\n" ::: "memory");

    for (int c=0; c<NCH; c++){
        if (c+1 < NCH) loadChunk(c+1, (c+1)&1);
        asm volatile("cp.async.commit_group;\n" ::: "memory");
        asm volatile("cp.async.wait_group 1;\n" ::: "memory");
        __syncthreads();
        int buf = c & 1;

        #pragma unroll 4
        for (int s=0; s<TCHUNK; s++){
            float dtv = s_dt[buf][s][dl];
            float xiv = s_xi[buf][s][dl];
            float Bt  = s_bc[buf][s][n];
            float Ct  = s_bc[buf][s][16+n];
            float dA  = __expf(dtv * a);
            h = fmaf(dA, h, dtv*Bt*xiv);
            float p = h*Ct;
            p += __shfl_xor_sync(0xffffffffu, p, 8);
            p += __shfl_xor_sync(0xffffffffu, p, 4);
            p += __shfl_xor_sync(0xffffffffu, p, 2);
            p += __shfl_xor_sync(0xffffffffu, p, 1);
            if (n==0){
                float zv = s_z[buf][s][dl];
                float yv = (p + xiv*Dv) * zv / (1.f + __expf(-zv));
                s_y[buf][s][dl] = f2b(yv);
            }
        }
        __syncthreads();

        {   // coalesced writeback: 64 rows x 16 bf16 (32B), 4 threads/row x 8B
            int row = tid >> 2, seg = tid & 3;
            int trow = (dir==0) ? c*TCHUNK+row : (LL-1) - (c*TCHUNK+row);
            long tok = (long)b*LL + trow;
            uint2 v = *reinterpret_cast<uint2*>(&s_y[buf][row][seg*4]);
            *reinterpret_cast<uint2*>(&g_ycat_bf[tok*2*DI + dir*DI + d0 + seg*4]) = v;
        }
    }
}

// ---------------- host launcher --------------------------------------------
extern "C" void kernel_launch(void* const* d_in, const int* in_sizes, int n_in,
                              void* d_out, int out_size){
    const float* x      = (const float*)d_in[0];
    const float* ln_g   = (const float*)d_in[1];
    const float* ln_b   = (const float*)d_in[2];
    const float* proj_w = (const float*)d_in[3];
    const float* proj_b = (const float*)d_in[4];
    const float* P[2][9];
    for (int dir=0; dir<2; dir++)
        for (int i=0;i<9;i++)
            P[dir][i] = (const float*)d_in[5 + dir*9 + i];

    float   *p_xz,*p_xdbl,*p_dt,*p_dtb;
    bf16raw *p_xn,*p_xib,*p_xdblb,*p_ycat,*p_ycb;
    bf16raw *w_in,*w_xp,*w_dt,*w_cat,*w_pj;
    cudaGetSymbolAddress((void**)&p_xz,    g_xz);
    cudaGetSymbolAddress((void**)&p_xdbl,  g_xdbl);
    cudaGetSymbolAddress((void**)&p_dt,    g_dt);
    cudaGetSymbolAddress((void**)&p_dtb,   g_dtb);
    cudaGetSymbolAddress((void**)&p_xn,    g_xn_bf);
    cudaGetSymbolAddress((void**)&p_xib,   g_xi_bf);
    cudaGetSymbolAddress((void**)&p_xdblb, g_xdbl_bf);
    cudaGetSymbolAddress((void**)&p_ycat,  g_ycat_bf);
    cudaGetSymbolAddress((void**)&p_ycb,   g_yc_bf);
    cudaGetSymbolAddress((void**)&w_in,    g_w_in);
    cudaGetSymbolAddress((void**)&w_xp,    g_w_xp);
    cudaGetSymbolAddress((void**)&w_dt,    g_w_dt);
    cudaGetSymbolAddress((void**)&w_cat,   g_w_cat);
    cudaGetSymbolAddress((void**)&w_pj,    g_w_pj);

    // 0. fused weight conversion
    {
        CvtArgs a;
        const float* srcs[9] = {P[0][0], P[1][0], P[0][3], P[1][3], P[0][4],
                                P[1][4], P[0][8], P[1][8], proj_w};
        bf16raw* dsts[9] = {w_in, w_in+DM*2*DI, w_xp, w_xp+DI*64, w_dt,
                            w_dt+32*DI, w_cat, w_cat+DI*DM, w_pj};
        int sizes[9] = {DM*2*DI, DM*2*DI, DI*64, DI*64, 32*DI,
                        32*DI, DI*DM, DI*DM, DM*DM};
        int acc = 0;
        for (int i=0;i<9;i++){ a.s[i]=srcs[i]; a.d[i]=dsts[i]; a.off[i]=acc; acc += sizes[i]/4; }
        a.off[9] = acc;
        cvt_all_kernel<<<(acc+255)/256, 256>>>(a, acc);
    }
    pack_dtb_kernel<<<(2*DI+255)/256, 256>>>(P[0][5], P[1][5]);

    // 1. layernorm -> bf16
    ln_kernel<<<NTOK, 256>>>(x, ln_g, ln_b);

    // 2. in-proj: xz = xn @ in_w  (4096 x 2048, K=512), dirs batched in z
    hgemm<<<dim3(2*DI/128, NTOK/128, 2), 256>>>(
        p_xn, 0, DM,
        w_in, (long)DM*2*DI, 2*DI,
        p_xz, (long)NTOK*2*DI, 2*DI,
        nullptr, 0,
        2*DI, DM, nullptr, 0, nullptr, 0, 0);

    // 3. conv + SiLU
    conv_kernel<<<dim3(NTOK*DI/256,1,2), 256>>>(P[0][1], P[0][2], P[1][1], P[1][2]);

    // 4. x_proj: xdbl = xi @ xproj_w  (4096 x 64, K=1024) + bf16 shadow
    hgemm<<<dim3(1, NTOK/128, 2), 256>>>(
        p_xib, (long)NTOK*DI, DI,
        w_xp,  (long)DI*64,   64,
        p_xdbl,(long)NTOK*64, 64,
        p_xdblb,(long)NTOK*64,
        64, DI, nullptr, 0, nullptr, 0, 0);

    // 5. dt = softplus(xdbl[:, :32] @ dt_w + dt_b)  (4096 x 1024, K=32)
    hgemm<<<dim3(DI/128, NTOK/128, 2), 256>>>(
        p_xdblb,(long)NTOK*64, 64,
        w_dt,   (long)32*DI,   DI,
        p_dt,   (long)NTOK*DI, DI,
        nullptr, 0,
        DI, 32, p_dtb, DI, nullptr, 0, 2);

    // 6. selective scan (smem-staged) -> ycat bf16
    scan_kernel<<<dim3(DI/CH, BB, 2), 256>>>(P[0][6], P[0][7], P[1][6], P[1][7]);

    // 7. yc = [y_f|y_b] @ [f_out_w; b_out_w]  (4096 x 512, K=2048) -> bf16
    hgemm<<<dim3(DM/128, NTOK/128, 1), 256>>>(
        p_ycat, 0, 2*DI,
        w_cat,  0, DM,
        nullptr, 0, DM,
        p_ycb, 0,
        DM, 2*DI, nullptr, 0, nullptr, 0, 0);

    // 8. out = yc @ proj_w + proj_b + x  (4096 x 512, K=512)
    hgemm<<<dim3(DM/128, NTOK/128, 1), 256>>>(
        p_ycb, 0, DM,
        w_pj,  0, DM,
        (float*)d_out, 0, DM,
        nullptr, 0,
        DM, DM, proj_b, 0, x, DM, 3);
}

// round 4
// speedup vs baseline: 13.6158x; 1.6741x over previous
#include <cuda_runtime.h>
#include <cuda_bf16.h>
#include <math.h>

#define BB 2
#define LL 2048
#define DM 512
#define DI 1024
#define DS 16
#define NTOK (BB*LL)   // 4096
#define TCHUNK 32
#define CH 16

typedef unsigned short bf16raw;

static __device__ __forceinline__ bf16raw f2b(float x){
    __nv_bfloat16 h = __float2bfloat16_rn(x);
    return *reinterpret_cast<bf16raw*>(&h);
}
static __device__ __forceinline__ void cp16(void* dst, const void* src){
    unsigned sa = (unsigned)__cvta_generic_to_shared(dst);
    asm volatile("cp.async.cg.shared.global [%0], [%1], 16;" :: "r"(sa), "l"(src));
}

// ---------------- scratch -------------------------------------------------
__device__ float   g_xz[2][NTOK*2*DI];       // in-proj out (xi|z)
__device__ float   g_xi[2][NTOK*DI];         // conv+silu out (fp32 for scan)
__device__ float   g_xdbl[2][NTOK*64];       // x_proj out (fp32 for scan B/C)
__device__ float   g_dt[2][NTOK*DI];         // softplus(dt)
__device__ float   g_dtb[2][DI];             // dt bias packed
__device__ bf16raw g_xn_bf[NTOK*DM];         // LN out, bf16 (GEMM1 A)
__device__ bf16raw g_xi_bf[2][NTOK*DI];      // conv out bf16 (GEMM2 A)
__device__ bf16raw g_xdbl_bf[2][NTOK*64];    // GEMM3 A
__device__ bf16raw g_ycat_bf[NTOK*2*DI];     // [tok][dir*DI+d]  (GEMM4 A)
__device__ bf16raw g_yc_bf[NTOK*DM];         // GEMM5 A
// bf16 weights
__device__ bf16raw g_w_in[2][DM*2*DI];
__device__ bf16raw g_w_xp[2][DI*64];
__device__ bf16raw g_w_dt[2][32*DI];
__device__ bf16raw g_w_cat[2*DI*DM];
__device__ bf16raw g_w_pj[DM*DM];

// ---------------- fused fp32 -> bf16 weight conversion ---------------------
struct CvtArgs { const float* s[9]; bf16raw* d[9]; int off[10]; };

__global__ void cvt_all_kernel(CvtArgs a, int total4){
    int i = blockIdx.x*blockDim.x + threadIdx.x;
    if (i >= total4) return;
    int seg = 0;
    while (i >= a.off[seg+1]) seg++;
    int j = (i - a.off[seg])*4;
    float4 v = *(const float4*)(a.s[seg] + j);
    bf16raw* d = a.d[seg] + j;
    d[0]=f2b(v.x); d[1]=f2b(v.y); d[2]=f2b(v.z); d[3]=f2b(v.w);
}

__global__ void pack_dtb_kernel(const float* __restrict__ f, const float* __restrict__ b){
    int i = blockIdx.x*blockDim.x + threadIdx.x;
    if (i < DI)            g_dtb[0][i]    = f[i];
    else if (i < 2*DI)     g_dtb[1][i-DI] = b[i-DI];
}

// ---------------- layernorm (writes bf16) ---------------------------------
__global__ void ln_kernel(const float* __restrict__ x,
                          const float* __restrict__ g,
                          const float* __restrict__ b) {
    int row = blockIdx.x;
    const float* xr = x + (long)row*DM;
    int tid = threadIdx.x;
    float v0 = xr[tid], v1 = xr[tid+256];
    __shared__ float s1[256], s2[256];
    s1[tid] = v0+v1; s2[tid] = v0*v0+v1*v1;
    __syncthreads();
    for (int o=128;o>0;o>>=1){
        if (tid<o){ s1[tid]+=s1[tid+o]; s2[tid]+=s2[tid+o]; }
        __syncthreads();
    }
    float mu = s1[0]*(1.0f/DM);
    float var = s2[0]*(1.0f/DM) - mu*mu;
    float rs = rsqrtf(var + 1e-5f);
    g_xn_bf[(long)row*DM+tid]     = f2b((v0-mu)*rs*g[tid]     + b[tid]);
    g_xn_bf[(long)row*DM+tid+256] = f2b((v1-mu)*rs*g[tid+256] + b[tid+256]);
}

// ---------------- bf16 tensor-core GEMM 128x128x32 -------------------------
__global__ __launch_bounds__(256) void hgemm(
    const bf16raw* __restrict__ Ag, long sA, int lda,
    const bf16raw* __restrict__ Bg, long sB, int ldb,
    float* __restrict__ Cg, long sC, int ldc,
    bf16raw* __restrict__ Obg, long sO,
    int N, int K,
    const float* __restrict__ biasg, long sbias,
    const float* __restrict__ res, int ldres,
    int epi)
{
    const bf16raw* A = Ag + sA*blockIdx.z;
    const bf16raw* B = Bg + sB*blockIdx.z;
    float* C   = Cg  ? Cg  + sC*blockIdx.z : nullptr;
    bf16raw* Ob = Obg ? Obg + sO*blockIdx.z : nullptr;
    const float* bias = biasg ? biasg + sbias*blockIdx.z : nullptr;

    __shared__ bf16raw As[2][128*40];
    __shared__ bf16raw Bs[2][32*128];

    int tid = threadIdx.x;
    int lane = tid & 31, wid = tid >> 5;
    int warp_m = wid & 3, warp_n = wid >> 2;
    int bm = blockIdx.y*128, bn = blockIdx.x*128;

    float acc[2][8][4];
    #pragma unroll
    for (int a=0;a<2;a++) for (int b2=0;b2<8;b2++) for (int c=0;c<4;c++) acc[a][b2][c]=0.f;

    int KT = K >> 5;

    auto loadTile = [&](int kt, int buf){
        int k0 = kt*32;
        #pragma unroll
        for (int i=0;i<2;i++){
            int q = tid + i*256;
            int r = q>>2, c = q&3;
            const bf16raw* src = A + (long)(bm+r)*lda + k0 + c*8;
            unsigned sa = (unsigned)__cvta_generic_to_shared(&As[buf][r*40 + c*8]);
            asm volatile("cp.async.cg.shared.global [%0], [%1], 16;\n" :: "r"(sa), "l"(src));
        }
        #pragma unroll
        for (int i=0;i<2;i++){
            int q = tid + i*256;
            int r = q>>4, c = q&15;
            int gcol = bn + c*8;
            const bf16raw* src = B + (long)(k0+r)*ldb + gcol;
            unsigned sa = (unsigned)__cvta_generic_to_shared(&Bs[buf][r*128 + ((c ^ (r&7))*8)]);
            int sz = (gcol < N) ? 16 : 0;
            asm volatile("cp.async.cg.shared.global [%0], [%1], 16, %2;\n" :: "r"(sa), "l"(src), "r"(sz));
        }
    };

    loadTile(0, 0);
    asm volatile("cp.async.commit_group;\n" ::: "memory");

    for (int kt=0; kt<KT; kt++){
        if (kt+1 < KT) loadTile(kt+1, (kt+1)&1);
        asm volatile("cp.async.commit_group;\n" ::: "memory");
        asm volatile("cp.async.wait_group 1;\n" ::: "memory");
        __syncthreads();
        int buf = kt & 1;

        #pragma unroll
        for (int ks=0; ks<2; ks++){
            unsigned af[2][4];
            #pragma unroll
            for (int mt=0; mt<2; mt++){
                int row = warp_m*32 + mt*16 + (lane&15);
                int chunk = ks*2 + (lane>>4);
                unsigned addr = (unsigned)__cvta_generic_to_shared(&As[buf][row*40 + chunk*8]);
                asm volatile("ldmatrix.sync.aligned.m8n8.x4.shared.b16 {%0,%1,%2,%3}, [%4];"
                    : "=r"(af[mt][0]),"=r"(af[mt][1]),"=r"(af[mt][2]),"=r"(af[mt][3]) : "r"(addr));
            }
            unsigned bfm[8][2];
            #pragma unroll
            for (int jn=0; jn<4; jn++){
                int row = ks*16 + (lane&15);
                int c = warp_n*8 + jn*2 + (lane>>4);
                unsigned addr = (unsigned)__cvta_generic_to_shared(&Bs[buf][row*128 + ((c ^ (row&7))*8)]);
                unsigned r0,r1,r2,r3;
                asm volatile("ldmatrix.sync.aligned.m8n8.x4.trans.shared.b16 {%0,%1,%2,%3}, [%4];"
                    : "=r"(r0),"=r"(r1),"=r"(r2),"=r"(r3) : "r"(addr));
                bfm[jn*2][0]=r0;   bfm[jn*2][1]=r1;
                bfm[jn*2+1][0]=r2; bfm[jn*2+1][1]=r3;
            }
            #pragma unroll
            for (int mt=0; mt<2; mt++)
                #pragma unroll
                for (int nt=0; nt<8; nt++){
                    asm volatile("mma.sync.aligned.m16n8k16.row.col.f32.bf16.bf16.f32 "
                        "{%0,%1,%2,%3}, {%4,%5,%6,%7}, {%8,%9}, {%0,%1,%2,%3};"
                        : "+f"(acc[mt][nt][0]),"+f"(acc[mt][nt][1]),
                          "+f"(acc[mt][nt][2]),"+f"(acc[mt][nt][3])
                        : "r"(af[mt][0]),"r"(af[mt][1]),"r"(af[mt][2]),"r"(af[mt][3]),
                          "r"(bfm[nt][0]),"r"(bfm[nt][1]));
                }
        }
        __syncthreads();
    }

    #pragma unroll
    for (int mt=0; mt<2; mt++){
        #pragma unroll
        for (int i2=0; i2<2; i2++){
            long r = bm + warp_m*32 + mt*16 + (lane>>2) + i2*8;
            #pragma unroll
            for (int nt=0; nt<8; nt++){
                int cbase = bn + warp_n*64 + nt*8 + (lane&3)*2;
                #pragma unroll
                for (int j=0; j<2; j++){
                    int c = cbase + j;
                    if (c >= N) continue;
                    float v = acc[mt][nt][i2*2+j];
                    if (epi==2){ v += bias[c]; v = (v>20.f)? v : log1pf(expf(v)); }
                    else if (epi==3){ v += bias[c] + res[r*ldres + c]; }
                    if (C)  C[r*ldc + c] = v;
                    if (Ob) Ob[r*ldc + c] = f2b(v);
                }
            }
        }
    }
}

// ---------------- depthwise conv + SiLU (both dirs via grid.z) -------------
__global__ void conv_kernel(const float* __restrict__ wf, const float* __restrict__ biasf,
                            const float* __restrict__ wb, const float* __restrict__ biasb){
    int dir = blockIdx.z;
    const float* w    = dir ? wb : wf;
    const float* bias = dir ? biasb : biasf;
    int idx = blockIdx.x*blockDim.x + threadIdx.x;
    int d = idx & (DI-1);
    int t = (idx >> 10) & (LL-1);
    int b = idx >> 21;
    const float* xz = g_xz[dir];
    float acc = bias[d];
    #pragma unroll
    for (int j=0;j<4;j++){
        int tt = (dir==0) ? (t-3+j) : (t+3-j);
        if (tt>=0 && tt<LL)
            acc = fmaf(w[d*4+j], xz[((long)(b*LL+tt)*2*DI) + d], acc);
    }
    float s = acc / (1.f + __expf(-acc));
    g_xi[dir][idx]    = s;
    g_xi_bf[dir][idx] = f2b(s);
}

// ---------------- selective scan: deferred-reduction, smem-staged ----------
// block = 256 threads, CH=16 channels of one (batch, dir).
// grid = (DI/CH=64, BB, 2).  Dynamic smem (56 KB).
struct ScanSmem {
    float dt[2][TCHUNK][CH];
    float xi[2][TCHUNK][CH];
    float z [2][TCHUNK][CH];
    float bc[2][TCHUNK][32];
    float p [TCHUNK][CH][17];   // h*C partials, pad 17 -> conflict-free
};

__global__ __launch_bounds__(256) void scan_kernel(
    const float* __restrict__ fA, const float* __restrict__ fD,
    const float* __restrict__ bA, const float* __restrict__ bD)
{
    extern __shared__ char smem_raw[];
    ScanSmem* S = reinterpret_cast<ScanSmem*>(smem_raw);

    int dir = blockIdx.z;
    int b   = blockIdx.y;
    int d0  = blockIdx.x * CH;
    const float* A_log = dir ? bA : fA;
    const float* Dp    = dir ? bD : fD;

    int tid  = threadIdx.x;
    int wid  = tid >> 5, lane = tid & 31;
    int half = lane >> 4, n = lane & 15;
    int dl   = wid*2 + half;

    float a    = -expf(A_log[(d0+dl)*DS + n]);
    float Dv_r = Dp[d0 + (tid & 15)];           // for reduction phase

    const float* dtp = g_dt[dir];
    const float* xip = g_xi[dir];
    const float* xzp = g_xz[dir];
    const float* bcp = g_xdbl[dir];

    const int NCH = LL / TCHUNK;   // 64 chunks

    auto loadChunk = [&](int c, int buf){
        if (tid < 128){   // dt/xi/z : 32 rows x 16 floats = 4 x 16B per row
            int row = tid >> 2, seg = tid & 3;
            int trow = (dir==0) ? c*TCHUNK+row : (LL-1) - (c*TCHUNK+row);
            long tok = (long)b*LL + trow;
            cp16(&S->dt[buf][row][seg*4], dtp + tok*DI + d0 + seg*4);
            cp16(&S->xi[buf][row][seg*4], xip + tok*DI + d0 + seg*4);
            cp16(&S->z [buf][row][seg*4], xzp + tok*2*DI + DI + d0 + seg*4);
        }
        {   // B|C : 32 rows x 32 floats = 8 x 16B per row
            int row = tid >> 3, seg = tid & 7;
            int trow = (dir==0) ? c*TCHUNK+row : (LL-1) - (c*TCHUNK+row);
            long tok = (long)b*LL + trow;
            cp16(&S->bc[buf][row][seg*4], bcp + tok*64 + 32 + seg*4);
        }
    };

    float h = 0.f;
    loadChunk(0, 0);
    asm volatile("cp.async.commit_group;\n" ::: "memory");

    for (int c=0; c<NCH; c++){
        if (c+1 < NCH) loadChunk(c+1, (c+1)&1);
        asm volatile("cp.async.commit_group;\n" ::: "memory");
        asm volatile("cp.async.wait_group 1;\n" ::: "memory");
        __syncthreads();
        int buf = c & 1;

        // ---- serial recurrence: only h-FMA on the chain, no shfl ----
        #pragma unroll
        for (int s=0; s<TCHUNK; s++){
            float dtv = S->dt[buf][s][dl];
            float xiv = S->xi[buf][s][dl];
            float Bt  = S->bc[buf][s][n];
            float Ct  = S->bc[buf][s][16+n];
            float dA  = __expf(dtv * a);
            h = fmaf(dA, h, dtv*xiv*Bt);
            S->p[s][dl][n] = h * Ct;
        }
        __syncthreads();

        // ---- parallel reduction over n + epilogue + coalesced store ----
        #pragma unroll
        for (int rep=0; rep<2; rep++){
            int o  = tid + rep*256;        // 512 outputs
            int s  = o >> 4, dlo = o & 15;
            float sum = 0.f;
            #pragma unroll
            for (int k=0;k<16;k++) sum += S->p[s][dlo][k];
            float xiv = S->xi[buf][s][dlo];
            float zv  = S->z [buf][s][dlo];
            float yv  = (sum + xiv*Dv_r) * zv / (1.f + __expf(-zv));
            int trow  = (dir==0) ? c*TCHUNK+s : (LL-1) - (c*TCHUNK+s);
            g_ycat_bf[((long)b*LL + trow)*2*DI + dir*DI + d0 + dlo] = f2b(yv);
        }
        __syncthreads();
    }
}

// ---------------- host launcher --------------------------------------------
extern "C" void kernel_launch(void* const* d_in, const int* in_sizes, int n_in,
                              void* d_out, int out_size){
    const float* x      = (const float*)d_in[0];
    const float* ln_g   = (const float*)d_in[1];
    const float* ln_b   = (const float*)d_in[2];
    const float* proj_w = (const float*)d_in[3];
    const float* proj_b = (const float*)d_in[4];
    const float* P[2][9];
    for (int dir=0; dir<2; dir++)
        for (int i=0;i<9;i++)
            P[dir][i] = (const float*)d_in[5 + dir*9 + i];

    float   *p_xz,*p_xdbl,*p_dt,*p_dtb;
    bf16raw *p_xn,*p_xib,*p_xdblb,*p_ycat,*p_ycb;
    bf16raw *w_in,*w_xp,*w_dt,*w_cat,*w_pj;
    cudaGetSymbolAddress((void**)&p_xz,    g_xz);
    cudaGetSymbolAddress((void**)&p_xdbl,  g_xdbl);
    cudaGetSymbolAddress((void**)&p_dt,    g_dt);
    cudaGetSymbolAddress((void**)&p_dtb,   g_dtb);
    cudaGetSymbolAddress((void**)&p_xn,    g_xn_bf);
    cudaGetSymbolAddress((void**)&p_xib,   g_xi_bf);
    cudaGetSymbolAddress((void**)&p_xdblb, g_xdbl_bf);
    cudaGetSymbolAddress((void**)&p_ycat,  g_ycat_bf);
    cudaGetSymbolAddress((void**)&p_ycb,   g_yc_bf);
    cudaGetSymbolAddress((void**)&w_in,    g_w_in);
    cudaGetSymbolAddress((void**)&w_xp,    g_w_xp);
    cudaGetSymbolAddress((void**)&w_dt,    g_w_dt);
    cudaGetSymbolAddress((void**)&w_cat,   g_w_cat);
    cudaGetSymbolAddress((void**)&w_pj,    g_w_pj);

    // 0. fused weight conversion
    {
        CvtArgs a;
        const float* srcs[9] = {P[0][0], P[1][0], P[0][3], P[1][3], P[0][4],
                                P[1][4], P[0][8], P[1][8], proj_w};
        bf16raw* dsts[9] = {w_in, w_in+DM*2*DI, w_xp, w_xp+DI*64, w_dt,
                            w_dt+32*DI, w_cat, w_cat+DI*DM, w_pj};
        int sizes[9] = {DM*2*DI, DM*2*DI, DI*64, DI*64, 32*DI,
                        32*DI, DI*DM, DI*DM, DM*DM};
        int acc = 0;
        for (int i=0;i<9;i++){ a.s[i]=srcs[i]; a.d[i]=dsts[i]; a.off[i]=acc; acc += sizes[i]/4; }
        a.off[9] = acc;
        cvt_all_kernel<<<(acc+255)/256, 256>>>(a, acc);
    }
    pack_dtb_kernel<<<(2*DI+255)/256, 256>>>(P[0][5], P[1][5]);

    // 1. layernorm -> bf16
    ln_kernel<<<NTOK, 256>>>(x, ln_g, ln_b);

    // 2. in-proj: xz = xn @ in_w  (4096 x 2048, K=512), dirs batched in z
    hgemm<<<dim3(2*DI/128, NTOK/128, 2), 256>>>(
        p_xn, 0, DM,
        w_in, (long)DM*2*DI, 2*DI,
        p_xz, (long)NTOK*2*DI, 2*DI,
        nullptr, 0,
        2*DI, DM, nullptr, 0, nullptr, 0, 0);

    // 3. conv + SiLU
    conv_kernel<<<dim3(NTOK*DI/256,1,2), 256>>>(P[0][1], P[0][2], P[1][1], P[1][2]);

    // 4. x_proj: xdbl = xi @ xproj_w  (4096 x 64, K=1024) + bf16 shadow
    hgemm<<<dim3(1, NTOK/128, 2), 256>>>(
        p_xib, (long)NTOK*DI, DI,
        w_xp,  (long)DI*64,   64,
        p_xdbl,(long)NTOK*64, 64,
        p_xdblb,(long)NTOK*64,
        64, DI, nullptr, 0, nullptr, 0, 0);

    // 5. dt = softplus(xdbl[:, :32] @ dt_w + dt_b)  (4096 x 1024, K=32)
    hgemm<<<dim3(DI/128, NTOK/128, 2), 256>>>(
        p_xdblb,(long)NTOK*64, 64,
        w_dt,   (long)32*DI,   DI,
        p_dt,   (long)NTOK*DI, DI,
        nullptr, 0,
        DI, 32, p_dtb, DI, nullptr, 0, 2);

    // 6. selective scan (deferred reduction) -> ycat bf16
    cudaFuncSetAttribute(scan_kernel, cudaFuncAttributeMaxDynamicSharedMemorySize,
                         (int)sizeof(ScanSmem));
    scan_kernel<<<dim3(DI/CH, BB, 2), 256, sizeof(ScanSmem)>>>(
        P[0][6], P[0][7], P[1][6], P[1][7]);

    // 7. yc = [y_f|y_b] @ [f_out_w; b_out_w]  (4096 x 512, K=2048) -> bf16
    hgemm<<<dim3(DM/128, NTOK/128, 1), 256>>>(
        p_ycat, 0, 2*DI,
        w_cat,  0, DM,
        nullptr, 0, DM,
        p_ycb, 0,
        DM, 2*DI, nullptr, 0, nullptr, 0, 0);

    // 8. out = yc @ proj_w + proj_b + x  (4096 x 512, K=512)
    hgemm<<<dim3(DM/128, NTOK/128, 1), 256>>>(
        p_ycb, 0, DM,
        w_pj,  0, DM,
        (float*)d_out, 0, DM,
        nullptr, 0,
        DM, DM, proj_b, 0, x, DM, 3);
}

// round 7
// speedup vs baseline: 13.8443x; 1.0168x over previous
#include <cuda_runtime.h>
#include <cuda_bf16.h>
#include <stdint.h>
#include <math.h>

#define BB 2
#define LL 2048
#define DM 512
#define DI 1024
#define DS 16
#define NTOK (BB*LL)   // 4096
#define TCHUNK 32
#define CH 16

typedef unsigned short bf16raw;

static __device__ __forceinline__ bf16raw f2b(float x){
    __nv_bfloat16 h = __float2bfloat16_rn(x);
    return *reinterpret_cast<bf16raw*>(&h);
}
static __device__ __forceinline__ void cp16(void* dst, const void* src){
    unsigned sa = (unsigned)__cvta_generic_to_shared(dst);
    asm volatile("cp.async.cg.shared.global [%0], [%1], 16;" :: "r"(sa), "l"(src));
}

// ---------------- scratch -------------------------------------------------
__device__ float   g_xz[2][NTOK*2*DI];
__device__ float   g_xi[2][NTOK*DI];
__device__ float   g_xdbl[2][NTOK*64];
__device__ float   g_dt[2][NTOK*DI];
__device__ float   g_dtb[2][DI];
__device__ bf16raw g_xn_bf[NTOK*DM];
__device__ bf16raw g_xi_bf[2][NTOK*DI];
__device__ bf16raw g_xdbl_bf[2][NTOK*64];
__device__ bf16raw g_ycat_bf[NTOK*2*DI];     // [tok][dir*DI+d]
__device__ bf16raw g_wcomb[2*DI*DM];         // folded Wcat@Wproj [2048][512]
// bf16 weights (all row-major, as in round 4)
__device__ bf16raw g_w_in[2][DM*2*DI];       // [512][2048] per dir
__device__ bf16raw g_w_xp[2][DI*64];
__device__ bf16raw g_w_dt[2][32*DI];
__device__ bf16raw g_w_cat[2*DI*DM];         // [f_out_w ; b_out_w] = [2048][512]
__device__ bf16raw g_w_pj[DM*DM];            // [512][512]

// ---------------- fused fp32 -> bf16 conversion ----------------------------
struct CvtArgs { const float* s[9]; bf16raw* d[9]; int off[10]; };

__global__ void cvt_all_kernel(CvtArgs a, int total4){
    int i = blockIdx.x*blockDim.x + threadIdx.x;
    if (i >= total4) return;
    int seg = 0;
    while (i >= a.off[seg+1]) seg++;
    int j = (i - a.off[seg])*4;
    float4 v = *(const float4*)(a.s[seg] + j);
    bf16raw* d = a.d[seg] + j;
    d[0]=f2b(v.x); d[1]=f2b(v.y); d[2]=f2b(v.z); d[3]=f2b(v.w);
}

__global__ void pack_dtb_kernel(const float* __restrict__ f, const float* __restrict__ b){
    int i = blockIdx.x*blockDim.x + threadIdx.x;
    if (i < DI)            g_dtb[0][i]    = f[i];
    else if (i < 2*DI)     g_dtb[1][i-DI] = b[i-DI];
}

// ---------------- layernorm (writes bf16) ---------------------------------
__global__ void ln_kernel(const float* __restrict__ x,
                          const float* __restrict__ g,
                          const float* __restrict__ b) {
    int row = blockIdx.x;
    const float* xr = x + (long)row*DM;
    int tid = threadIdx.x;
    float v0 = xr[tid], v1 = xr[tid+256];
    __shared__ float s1[256], s2[256];
    s1[tid] = v0+v1; s2[tid] = v0*v0+v1*v1;
    __syncthreads();
    for (int o=128;o>0;o>>=1){
        if (tid<o){ s1[tid]+=s1[tid+o]; s2[tid]+=s2[tid+o]; }
        __syncthreads();
    }
    float mu = s1[0]*(1.0f/DM);
    float var = s2[0]*(1.0f/DM) - mu*mu;
    float rs = rsqrtf(var + 1e-5f);
    g_xn_bf[(long)row*DM+tid]     = f2b((v0-mu)*rs*g[tid]     + b[tid]);
    g_xn_bf[(long)row*DM+tid+256] = f2b((v1-mu)*rs*g[tid+256] + b[tid+256]);
}

// ---------------- bf16 tensor-core GEMM, 128x128 tile, templated BK --------
// C[M,N] = A[M,K] @ B[K,N], A/B bf16 row-major, fp32 accumulate.
// epi: 0 plain, 2 softplus(v+bias), 3 v+bias+res. Optional bf16 shadow Ob.
template<int BK>
__global__ __launch_bounds__(256) void hgemm(
    const bf16raw* __restrict__ Ag, long sA, int lda,
    const bf16raw* __restrict__ Bg, long sB, int ldb,
    float* __restrict__ Cg, long sC, int ldc,
    bf16raw* __restrict__ Obg, long sO,
    int N, int K,
    const float* __restrict__ biasg, long sbias,
    const float* __restrict__ res, int ldres,
    int epi)
{
    const bf16raw* A = Ag + sA*blockIdx.z;
    const bf16raw* B = Bg + sB*blockIdx.z;
    float* C   = Cg  ? Cg  + sC*blockIdx.z : nullptr;
    bf16raw* Ob = Obg ? Obg + sO*blockIdx.z : nullptr;
    const float* bias = biasg ? biasg + sbias*blockIdx.z : nullptr;

    extern __shared__ __align__(16) bf16raw sdyn[];
    const int ABUF = 128*(BK+8);     // A rows padded by 8 halves
    const int BBUF = BK*128;
    bf16raw* As = sdyn;              // [2][ABUF]
    bf16raw* Bs = sdyn + 2*ABUF;     // [2][BBUF]

    int tid = threadIdx.x;
    int lane = tid & 31, wid = tid >> 5;
    int warp_m = wid & 3, warp_n = wid >> 2;     // 4 x 2 warps
    int bm = blockIdx.y*128, bn = blockIdx.x*128;

    float acc[2][8][4];
    #pragma unroll
    for (int a=0;a<2;a++) for (int b2=0;b2<8;b2++) for (int c=0;c<4;c++) acc[a][b2][c]=0.f;

    int KT = K / BK;
    const int CPR = BK/8;            // 16B chunks per A row

    auto loadTile = [&](int kt, int buf){
        int k0 = kt*BK;
        #pragma unroll
        for (int i=0;i<BK/16;i++){               // A: 128*(BK/8) chunks
            int q = tid + i*256;
            int r = q / CPR, c = q % CPR;
            const bf16raw* src = A + (long)(bm+r)*lda + k0 + c*8;
            unsigned sa = (unsigned)__cvta_generic_to_shared(&As[buf*ABUF + r*(BK+8) + c*8]);
            asm volatile("cp.async.cg.shared.global [%0], [%1], 16;\n" :: "r"(sa), "l"(src));
        }
        #pragma unroll
        for (int i=0;i<BK/16;i++){               // B: BK*16 chunks
            int q = tid + i*256;
            int r = q>>4, c = q&15;
            int gcol = bn + c*8;
            const bf16raw* src = B + (long)(k0+r)*ldb + gcol;
            unsigned sa = (unsigned)__cvta_generic_to_shared(&Bs[buf*BBUF + r*128 + ((c ^ (r&7))*8)]);
            int sz = (gcol < N) ? 16 : 0;
            asm volatile("cp.async.cg.shared.global [%0], [%1], 16, %2;\n" :: "r"(sa), "l"(src), "r"(sz));
        }
    };

    loadTile(0, 0);
    asm volatile("cp.async.commit_group;\n" ::: "memory");

    for (int kt=0; kt<KT; kt++){
        if (kt+1 < KT) loadTile(kt+1, (kt+1)&1);
        asm volatile("cp.async.commit_group;\n" ::: "memory");
        asm volatile("cp.async.wait_group 1;\n" ::: "memory");
        __syncthreads();
        int buf = kt & 1;

        #pragma unroll
        for (int ks=0; ks<BK/16; ks++){
            unsigned af[2][4];
            #pragma unroll
            for (int mt=0; mt<2; mt++){
                int row = warp_m*32 + mt*16 + (lane&15);
                int chunk = ks*2 + (lane>>4);
                unsigned addr = (unsigned)__cvta_generic_to_shared(&As[buf*ABUF + row*(BK+8) + chunk*8]);
                asm volatile("ldmatrix.sync.aligned.m8n8.x4.shared.b16 {%0,%1,%2,%3}, [%4];"
                    : "=r"(af[mt][0]),"=r"(af[mt][1]),"=r"(af[mt][2]),"=r"(af[mt][3]) : "r"(addr));
            }
            unsigned bfm[8][2];
            #pragma unroll
            for (int jn=0; jn<4; jn++){
                int row = ks*16 + (lane&15);
                int c = warp_n*8 + jn*2 + (lane>>4);
                unsigned addr = (unsigned)__cvta_generic_to_shared(&Bs[buf*BBUF + row*128 + ((c ^ (row&7))*8)]);
                unsigned r0,r1,r2,r3;
                asm volatile("ldmatrix.sync.aligned.m8n8.x4.trans.shared.b16 {%0,%1,%2,%3}, [%4];"
                    : "=r"(r0),"=r"(r1),"=r"(r2),"=r"(r3) : "r"(addr));
                bfm[jn*2][0]=r0;   bfm[jn*2][1]=r1;
                bfm[jn*2+1][0]=r2; bfm[jn*2+1][1]=r3;
            }
            #pragma unroll
            for (int mt=0; mt<2; mt++)
                #pragma unroll
                for (int nt=0; nt<8; nt++){
                    asm volatile("mma.sync.aligned.m16n8k16.row.col.f32.bf16.bf16.f32 "
                        "{%0,%1,%2,%3}, {%4,%5,%6,%7}, {%8,%9}, {%0,%1,%2,%3};"
                        : "+f"(acc[mt][nt][0]),"+f"(acc[mt][nt][1]),
                          "+f"(acc[mt][nt][2]),"+f"(acc[mt][nt][3])
                        : "r"(af[mt][0]),"r"(af[mt][1]),"r"(af[mt][2]),"r"(af[mt][3]),
                          "r"(bfm[nt][0]),"r"(bfm[nt][1]));
                }
        }
        __syncthreads();
    }

    #pragma unroll
    for (int mt=0; mt<2; mt++){
        #pragma unroll
        for (int i2=0; i2<2; i2++){
            long r = bm + warp_m*32 + mt*16 + (lane>>2) + i2*8;
            #pragma unroll
            for (int nt=0; nt<8; nt++){
                int cbase = bn + warp_n*64 + nt*8 + (lane&3)*2;
                #pragma unroll
                for (int j=0; j<2; j++){
                    int c = cbase + j;
                    if (c >= N) continue;
                    float v = acc[mt][nt][i2*2+j];
                    if (epi==2){ v += bias[c]; v = (v>20.f)? v : log1pf(expf(v)); }
                    else if (epi==3){ v += bias[c] + res[r*ldres + c]; }
                    if (C)  C[r*ldc + c] = v;
                    if (Ob) Ob[r*ldc + c] = f2b(v);
                }
            }
        }
    }
}

// ---------------- depthwise conv + SiLU (both dirs via grid.z) -------------
__global__ void conv_kernel(const float* __restrict__ wf, const float* __restrict__ biasf,
                            const float* __restrict__ wb, const float* __restrict__ biasb){
    int dir = blockIdx.z;
    const float* w    = dir ? wb : wf;
    const float* bias = dir ? biasb : biasf;
    int idx = blockIdx.x*blockDim.x + threadIdx.x;
    int d = idx & (DI-1);
    int t = (idx >> 10) & (LL-1);
    int b = idx >> 21;
    const float* xz = g_xz[dir];
    float acc = bias[d];
    #pragma unroll
    for (int j=0;j<4;j++){
        int tt = (dir==0) ? (t-3+j) : (t+3-j);
        if (tt>=0 && tt<LL)
            acc = fmaf(w[d*4+j], xz[((long)(b*LL+tt)*2*DI) + d], acc);
    }
    float s = acc / (1.f + __expf(-acc));
    g_xi[dir][idx]    = s;
    g_xi_bf[dir][idx] = f2b(s);
}

// ---------------- selective scan: deferred-reduction, smem-staged ----------
struct ScanSmem {
    float dt[2][TCHUNK][CH];
    float xi[2][TCHUNK][CH];
    float z [2][TCHUNK][CH];
    float bc[2][TCHUNK][32];
    float p [TCHUNK][CH][17];
};

__global__ __launch_bounds__(256) void scan_kernel(
    const float* __restrict__ fA, const float* __restrict__ fD,
    const float* __restrict__ bA, const float* __restrict__ bD)
{
    extern __shared__ char smem_raw[];
    ScanSmem* S = reinterpret_cast<ScanSmem*>(smem_raw);

    int dir = blockIdx.z;
    int b   = blockIdx.y;
    int d0  = blockIdx.x * CH;
    const float* A_log = dir ? bA : fA;
    const float* Dp    = dir ? bD : fD;

    int tid  = threadIdx.x;
    int wid  = tid >> 5, lane = tid & 31;
    int half = lane >> 4, n = lane & 15;
    int dl   = wid*2 + half;

    float a    = -expf(A_log[(d0+dl)*DS + n]);
    float Dv_r = Dp[d0 + (tid & 15)];

    const float* dtp = g_dt[dir];
    const float* xip = g_xi[dir];
    const float* xzp = g_xz[dir];
    const float* bcp = g_xdbl[dir];

    const int NCH = LL / TCHUNK;

    auto loadChunk = [&](int c, int buf){
        if (tid < 128){
            int row = tid >> 2, seg = tid & 3;
            int trow = (dir==0) ? c*TCHUNK+row : (LL-1) - (c*TCHUNK+row);
            long tok = (long)b*LL + trow;
            cp16(&S->dt[buf][row][seg*4], dtp + tok*DI + d0 + seg*4);
            cp16(&S->xi[buf][row][seg*4], xip + tok*DI + d0 + seg*4);
            cp16(&S->z [buf][row][seg*4], xzp + tok*2*DI + DI + d0 + seg*4);
        }
        {
            int row = tid >> 3, seg = tid & 7;
            int trow = (dir==0) ? c*TCHUNK+row : (LL-1) - (c*TCHUNK+row);
            long tok = (long)b*LL + trow;
            cp16(&S->bc[buf][row][seg*4], bcp + tok*64 + 32 + seg*4);
        }
    };

    float h = 0.f;
    loadChunk(0, 0);
    asm volatile("cp.async.commit_group;\n" ::: "memory");

    for (int c=0; c<NCH; c++){
        if (c+1 < NCH) loadChunk(c+1, (c+1)&1);
        asm volatile("cp.async.commit_group;\n" ::: "memory");
        asm volatile("cp.async.wait_group 1;\n" ::: "memory");
        __syncthreads();
        int buf = c & 1;

        #pragma unroll
        for (int s=0; s<TCHUNK; s++){
            float dtv = S->dt[buf][s][dl];
            float xiv = S->xi[buf][s][dl];
            float Bt  = S->bc[buf][s][n];
            float Ct  = S->bc[buf][s][16+n];
            float dA  = __expf(dtv * a);
            h = fmaf(dA, h, dtv*xiv*Bt);
            S->p[s][dl][n] = h * Ct;
        }
        __syncthreads();

        #pragma unroll
        for (int rep=0; rep<2; rep++){
            int o  = tid + rep*256;
            int s  = o >> 4, dlo = o & 15;
            float sum = 0.f;
            #pragma unroll
            for (int k=0;k<16;k++) sum += S->p[s][dlo][k];
            float xiv = S->xi[buf][s][dlo];
            float zv  = S->z [buf][s][dlo];
            float yv  = (sum + xiv*Dv_r) * zv / (1.f + __expf(-zv));
            int trow  = (dir==0) ? c*TCHUNK+s : (LL-1) - (c*TCHUNK+s);
            g_ycat_bf[((long)b*LL + trow)*2*DI + dir*DI + d0 + dlo] = f2b(yv);
        }
        __syncthreads();
    }
}

// ---------------- host launcher --------------------------------------------
extern "C" void kernel_launch(void* const* d_in, const int* in_sizes, int n_in,
                              void* d_out, int out_size){
    const float* x      = (const float*)d_in[0];
    const float* ln_g   = (const float*)d_in[1];
    const float* ln_b   = (const float*)d_in[2];
    const float* proj_w = (const float*)d_in[3];
    const float* proj_b = (const float*)d_in[4];
    const float* P[2][9];
    for (int dir=0; dir<2; dir++)
        for (int i=0;i<9;i++)
            P[dir][i] = (const float*)d_in[5 + dir*9 + i];

    float   *p_xz,*p_xdbl,*p_dt,*p_dtb;
    bf16raw *p_xn,*p_xib,*p_xdblb,*p_ycat,*p_wcomb;
    bf16raw *w_in,*w_xp,*w_dt,*w_cat,*w_pj;
    cudaGetSymbolAddress((void**)&p_xz,    g_xz);
    cudaGetSymbolAddress((void**)&p_xdbl,  g_xdbl);
    cudaGetSymbolAddress((void**)&p_dt,    g_dt);
    cudaGetSymbolAddress((void**)&p_dtb,   g_dtb);
    cudaGetSymbolAddress((void**)&p_xn,    g_xn_bf);
    cudaGetSymbolAddress((void**)&p_xib,   g_xi_bf);
    cudaGetSymbolAddress((void**)&p_xdblb, g_xdbl_bf);
    cudaGetSymbolAddress((void**)&p_ycat,  g_ycat_bf);
    cudaGetSymbolAddress((void**)&p_wcomb, g_wcomb);
    cudaGetSymbolAddress((void**)&w_in,    g_w_in);
    cudaGetSymbolAddress((void**)&w_xp,    g_w_xp);
    cudaGetSymbolAddress((void**)&w_dt,    g_w_dt);
    cudaGetSymbolAddress((void**)&w_cat,   g_w_cat);
    cudaGetSymbolAddress((void**)&w_pj,    g_w_pj);

    const int SMEM64 = (2*(128*72) + 2*(64*128))*2;   // 69632
    const int SMEM32 = (2*(128*40) + 2*(32*128))*2;   // 36864
    cudaFuncSetAttribute(hgemm<64>, cudaFuncAttributeMaxDynamicSharedMemorySize, SMEM64);
    cudaFuncSetAttribute(hgemm<32>, cudaFuncAttributeMaxDynamicSharedMemorySize, SMEM32);

    // 0. fused weight conversion (all row-major)
    {
        CvtArgs a;
        const float* srcs[9] = {P[0][0], P[1][0], P[0][3], P[1][3], P[0][4],
                                P[1][4], P[0][8], P[1][8], proj_w};
        bf16raw* dsts[9] = {w_in, w_in+DM*2*DI, w_xp, w_xp+DI*64, w_dt,
                            w_dt+32*DI, w_cat, w_cat+DI*DM, w_pj};
        int sizes[9] = {DM*2*DI, DM*2*DI, DI*64, DI*64, 32*DI,
                        32*DI, DI*DM, DI*DM, DM*DM};
        int acc = 0;
        for (int i=0;i<9;i++){ a.s[i]=srcs[i]; a.d[i]=dsts[i]; a.off[i]=acc; acc += sizes[i]/4; }
        a.off[9] = acc;
        cvt_all_kernel<<<(acc+255)/256, 256>>>(a, acc);
    }
    pack_dtb_kernel<<<(2*DI+255)/256, 256>>>(P[0][5], P[1][5]);

    // 0c. fold: Wcomb = [f_out_w; b_out_w] @ proj_w   (2048 x 512, K=512) -> bf16
    hgemm<64><<<dim3(DM/128, 2*DI/128, 1), 256, SMEM64>>>(
        w_cat, 0, DM,
        w_pj,  0, DM,
        nullptr, 0, DM,
        p_wcomb, 0,
        DM, DM, nullptr, 0, nullptr, 0, 0);

    // 1. layernorm -> bf16
    ln_kernel<<<NTOK, 256>>>(x, ln_g, ln_b);

    // 2. in-proj: xz = xn @ in_w  (4096 x 2048, K=512), dirs batched in z
    hgemm<64><<<dim3(2*DI/128, NTOK/128, 2), 256, SMEM64>>>(
        p_xn, 0, DM,
        w_in, (long)DM*2*DI, 2*DI,
        p_xz, (long)NTOK*2*DI, 2*DI,
        nullptr, 0,
        2*DI, DM, nullptr, 0, nullptr, 0, 0);

    // 3. conv + SiLU
    conv_kernel<<<dim3(NTOK*DI/256,1,2), 256>>>(P[0][1], P[0][2], P[1][1], P[1][2]);

    // 4. x_proj: xdbl = xi @ xproj_w  (4096 x 64, K=1024) + bf16 shadow
    hgemm<64><<<dim3(1, NTOK/128, 2), 256, SMEM64>>>(
        p_xib, (long)NTOK*DI, DI,
        w_xp,  (long)DI*64,   64,
        p_xdbl,(long)NTOK*64, 64,
        p_xdblb,(long)NTOK*64,
        64, DI, nullptr, 0, nullptr, 0, 0);

    // 5. dt = softplus(xdbl[:, :32] @ dt_w + dt_b)  (4096 x 1024, K=32)
    hgemm<32><<<dim3(DI/128, NTOK/128, 2), 256, SMEM32>>>(
        p_xdblb,(long)NTOK*64, 64,
        w_dt,   (long)32*DI,   DI,
        p_dt,   (long)NTOK*DI, DI,
        nullptr, 0,
        DI, 32, p_dtb, DI, nullptr, 0, 2);

    // 6. selective scan (deferred reduction) -> ycat bf16
    cudaFuncSetAttribute(scan_kernel, cudaFuncAttributeMaxDynamicSharedMemorySize,
                         (int)sizeof(ScanSmem));
    scan_kernel<<<dim3(DI/CH, BB, 2), 256, sizeof(ScanSmem)>>>(
        P[0][6], P[0][7], P[1][6], P[1][7]);

    // 7. out = ycat @ Wcomb + proj_b + x  (4096 x 512, K=2048)
    hgemm<64><<<dim3(DM/128, NTOK/128, 1), 256, SMEM64>>>(
        p_ycat, 0, 2*DI,
        p_wcomb, 0, DM,
        (float*)d_out, 0, DM,
        nullptr, 0,
        DM, 2*DI, proj_b, 0, x, DM, 3);
}